// round 5
// baseline (speedup 1.0000x reference)
#include <cuda_runtime.h>
#include <math.h>
#include <stdint.h>

#define VV 32000
#define EE 1024
#define HH 1024
#define BB 8
#define TT 512
#define MTOK 4096   // B*T
#define GK 1024     // K for both tensor GEMMs
#define NKCH 32     // K chunks of 32

#define RNN_NBLK 128

// ---------------- scratch (device globals; no allocation) ----------------
__device__ float g_xnorm[MTOK * EE];   // also reused as rounded-h1
__device__ float g_xp[MTOK * HH];
__device__ float g_h0[MTOK * HH];
__device__ float g_h1[MTOK * HH];
__device__ float g_act[MTOK * EE];
__device__ float g_embr[VV * EE];      // tf32-rounded emb (131 MB)
__device__ float g_wlr[EE * HH];       // tf32-rounded W_lin

__device__ volatile unsigned g_ready[RNN_NBLK];

// ---------------- helpers ----------------
__device__ __forceinline__ uint32_t smem_u32(const void* p) {
    uint32_t a;
    asm("{ .reg .u64 t; cvta.to.shared.u64 t, %1; cvt.u32.u64 %0, t; }"
        : "=r"(a) : "l"(p));
    return a;
}
__device__ __forceinline__ unsigned f2tf(float f) {
    unsigned u;
    asm("cvt.rna.tf32.f32 %0, %1;" : "=r"(u) : "f"(f));
    return u;
}
__device__ __forceinline__ void cp16(uint32_t d, const void* s) {
    asm volatile("cp.async.cg.shared.global [%0], [%1], 16;" :: "r"(d), "l"(s));
}
#define CP_COMMIT() asm volatile("cp.async.commit_group;" ::: "memory")
#define CP_WAIT(n)  asm volatile("cp.async.wait_group %0;" :: "n"(n) : "memory")

// ---------------- LayerNorm(emb[x]) ----------------
__global__ void ln_embed_kernel(const int* __restrict__ x,
                                const float* __restrict__ emb,
                                float* __restrict__ out) {
    int r = blockIdx.x;
    int tid = threadIdx.x;               // 256 threads
    int row = x[r];
    const float4* src = (const float4*)(emb + (size_t)row * EE);
    float4 v = src[tid];
    float s = v.x + v.y + v.z + v.w;
    float q = v.x * v.x + v.y * v.y + v.z * v.z + v.w * v.w;
    #pragma unroll
    for (int off = 16; off > 0; off >>= 1) {
        s += __shfl_xor_sync(0xffffffffu, s, off);
        q += __shfl_xor_sync(0xffffffffu, q, off);
    }
    __shared__ float sh_s[8], sh_q[8];
    int warp = tid >> 5, lane = tid & 31;
    if (lane == 0) { sh_s[warp] = s; sh_q[warp] = q; }
    __syncthreads();
    __shared__ float s_mu, s_inv;
    if (tid == 0) {
        float S = 0.f, Q = 0.f;
        #pragma unroll
        for (int i = 0; i < 8; i++) { S += sh_s[i]; Q += sh_q[i]; }
        float mu = S * (1.0f / EE);
        float var = Q * (1.0f / EE) - mu * mu;
        s_mu = mu;
        s_inv = rsqrtf(var + 1e-5f);
    }
    __syncthreads();
    float mu = s_mu, inv = s_inv;
    float4 o;
    o.x = (v.x - mu) * inv; o.y = (v.y - mu) * inv;
    o.z = (v.z - mu) * inv; o.w = (v.w - mu) * inv;
    ((float4*)(out + (size_t)r * EE))[tid] = o;
}

// ---------------- tf32 rounding pass ----------------
__global__ void tf32round_kernel(const float* __restrict__ src,
                                 float* __restrict__ dst, int n4) {
    int i = blockIdx.x * blockDim.x + threadIdx.x;
    if (i < n4) {
        float4 v = ((const float4*)src)[i];
        uint4 o = make_uint4(f2tf(v.x), f2tf(v.y), f2tf(v.z), f2tf(v.w));
        ((uint4*)dst)[i] = o;
    }
}

// ---------------- fp32 SGEMM (recurrence-feeding projections) ----------------
template <int MODE>  // 1: +bias
__global__ void sgemm_tn_kernel(const float* __restrict__ A,
                                const float* __restrict__ B,
                                const float* __restrict__ bias,
                                float* __restrict__ C,
                                int M, int N, int K) {
    __shared__ float As[16][132];
    __shared__ float Bs[16][132];

    const int tid = threadIdx.x;
    const int m0 = blockIdx.x * 128;
    const int n0 = blockIdx.y * 128;
    const int tx = tid & 15;
    const int ty = tid >> 4;
    const int lr = tid >> 2;
    const int lk = (tid & 3) * 4;

    float c[8][8];
    #pragma unroll
    for (int i = 0; i < 8; i++)
        #pragma unroll
        for (int j = 0; j < 8; j++) c[i][j] = 0.f;

    for (int kt = 0; kt < K; kt += 16) {
        __syncthreads();
        float4 a0 = *(const float4*)&A[(size_t)(m0 + lr) * K + kt + lk];
        float4 a1 = *(const float4*)&A[(size_t)(m0 + lr + 64) * K + kt + lk];
        float4 b0 = *(const float4*)&B[(size_t)(n0 + lr) * K + kt + lk];
        float4 b1 = *(const float4*)&B[(size_t)(n0 + lr + 64) * K + kt + lk];
        As[lk + 0][lr] = a0.x; As[lk + 1][lr] = a0.y; As[lk + 2][lr] = a0.z; As[lk + 3][lr] = a0.w;
        As[lk + 0][lr + 64] = a1.x; As[lk + 1][lr + 64] = a1.y; As[lk + 2][lr + 64] = a1.z; As[lk + 3][lr + 64] = a1.w;
        Bs[lk + 0][lr] = b0.x; Bs[lk + 1][lr] = b0.y; Bs[lk + 2][lr] = b0.z; Bs[lk + 3][lr] = b0.w;
        Bs[lk + 0][lr + 64] = b1.x; Bs[lk + 1][lr + 64] = b1.y; Bs[lk + 2][lr + 64] = b1.z; Bs[lk + 3][lr + 64] = b1.w;
        __syncthreads();
        #pragma unroll
        for (int k = 0; k < 16; k++) {
            float4 aA = *(const float4*)&As[k][ty * 8];
            float4 aB = *(const float4*)&As[k][ty * 8 + 4];
            float4 bA = *(const float4*)&Bs[k][tx * 8];
            float4 bB = *(const float4*)&Bs[k][tx * 8 + 4];
            float a[8] = {aA.x, aA.y, aA.z, aA.w, aB.x, aB.y, aB.z, aB.w};
            float b[8] = {bA.x, bA.y, bA.z, bA.w, bB.x, bB.y, bB.z, bB.w};
            #pragma unroll
            for (int i = 0; i < 8; i++)
                #pragma unroll
                for (int j = 0; j < 8; j++)
                    c[i][j] = fmaf(a[i], b[j], c[i][j]);
        }
    }

    float bb0[8];
    if (MODE != 0) {
        float4 t0 = *(const float4*)&bias[n0 + tx * 8];
        float4 t1 = *(const float4*)&bias[n0 + tx * 8 + 4];
        bb0[0] = t0.x; bb0[1] = t0.y; bb0[2] = t0.z; bb0[3] = t0.w;
        bb0[4] = t1.x; bb0[5] = t1.y; bb0[6] = t1.z; bb0[7] = t1.w;
    }

    #pragma unroll
    for (int i = 0; i < 8; i++) {
        int row = m0 + ty * 8 + i;
        float o[8];
        #pragma unroll
        for (int j = 0; j < 8; j++) {
            float v = c[i][j];
            if (MODE != 0) v += bb0[j];
            o[j] = v;
        }
        *(float4*)&C[(size_t)row * N + n0 + tx * 8] = make_float4(o[0], o[1], o[2], o[3]);
        *(float4*)&C[(size_t)row * N + n0 + tx * 8 + 4] = make_float4(o[4], o[5], o[6], o[7]);
    }
}

// ---------------- tf32 mma.sync GEMM v2 ----------------
// C[M,N] = A[M,K] * B[N,K]^T. Inputs MUST be pre-rounded to tf32 values.
// BM=256, BN=128, BK=32, 512 threads (warps 4M x 4N, warp tile 64x32).
// 4-stage cp.async pipeline, XOR-swizzled smem (row*128B, 16B chunk ^ (row&7)).
// MODE 0: plain; MODE 2: relu(x+bias) then tf32-rounded output.
#define V2_STAGES 4
#define V2_ABYTES (256 * 32 * 4)     // 32768
#define V2_BBYTES (128 * 32 * 4)     // 16384
#define V2_STAGE  (V2_ABYTES + V2_BBYTES)
#define V2_SMEM   (V2_STAGES * V2_STAGE)   // 196608

template <int MODE>
__global__ __launch_bounds__(512) void tf32v2_kernel(
        const float* __restrict__ A,
        const float* __restrict__ Bm,
        const float* __restrict__ bias,
        float* __restrict__ C,
        int N) {
    extern __shared__ char smem[];
    const uint32_t sb = smem_u32(smem);

    const int tid  = threadIdx.x;
    const int lane = tid & 31;
    const int warp = tid >> 5;
    const int g    = lane >> 2;
    const int tg   = lane & 3;
    const int wm   = warp & 3;     // M quadrant (64 rows)
    const int wn   = warp >> 2;    // N quadrant (32 cols)
    const int m0 = blockIdx.x * 256;
    const int n0 = blockIdx.y * 128;

    float acc[4][4][4];
    #pragma unroll
    for (int i = 0; i < 4; i++)
        #pragma unroll
        for (int j = 0; j < 4; j++)
            #pragma unroll
            for (int q = 0; q < 4; q++) acc[i][j][q] = 0.f;

    // ---- async copy of one stage ----
    auto issue = [&](int st, int kt) {
        uint32_t ab = sb + st * V2_STAGE;
        uint32_t bb = ab + V2_ABYTES;
        #pragma unroll
        for (int i = 0; i < 4; i++) {                 // A: 256x32 fl = 2048 chunks
            int idx = tid + i * 512;
            int row = idx >> 3, ch = idx & 7;
            int sw = ch ^ (row & 7);
            cp16(ab + row * 128 + sw * 16, &A[(size_t)(m0 + row) * GK + kt + ch * 4]);
        }
        #pragma unroll
        for (int i = 0; i < 2; i++) {                 // B: 128x32 fl = 1024 chunks
            int idx = tid + i * 512;
            int row = idx >> 3, ch = idx & 7;
            int sw = ch ^ (row & 7);
            cp16(bb + row * 128 + sw * 16, &Bm[(size_t)(n0 + row) * GK + kt + ch * 4]);
        }
        CP_COMMIT();
    };

    #pragma unroll
    for (int s = 0; s < V2_STAGES - 1; s++) issue(s, s * 32);

    for (int ci = 0; ci < NKCH; ci++) {
        CP_WAIT(V2_STAGES - 2);
        __syncthreads();
        if (ci + V2_STAGES - 1 < NKCH)
            issue((ci + V2_STAGES - 1) % V2_STAGES, (ci + V2_STAGES - 1) * 32);

        const char* ab = smem + (ci % V2_STAGES) * V2_STAGE;
        const char* bb = ab + V2_ABYTES;
        #pragma unroll
        for (int ks = 0; ks < 32; ks += 8) {
            const int grp = ks >> 2;
            const int sw0 = (grp ^ g) * 16;
            const int sw1 = ((grp + 1) ^ g) * 16;
            unsigned af[4][4];
            #pragma unroll
            for (int ma = 0; ma < 4; ma++) {
                int r = wm * 64 + ma * 16 + g;
                const char* p  = ab + r * 128 + tg * 4;
                const char* p2 = ab + (r + 8) * 128 + tg * 4;
                af[ma][0] = *(const unsigned*)(p  + sw0);
                af[ma][1] = *(const unsigned*)(p2 + sw0);
                af[ma][2] = *(const unsigned*)(p  + sw1);
                af[ma][3] = *(const unsigned*)(p2 + sw1);
            }
            unsigned bf[4][2];
            #pragma unroll
            for (int na = 0; na < 4; na++) {
                int n = wn * 32 + na * 8 + g;
                const char* p = bb + n * 128 + tg * 4;
                bf[na][0] = *(const unsigned*)(p + sw0);
                bf[na][1] = *(const unsigned*)(p + sw1);
            }
            #pragma unroll
            for (int ma = 0; ma < 4; ma++)
                #pragma unroll
                for (int na = 0; na < 4; na++) {
                    asm volatile(
                        "mma.sync.aligned.m16n8k8.row.col.f32.tf32.tf32.f32 "
                        "{%0,%1,%2,%3}, {%4,%5,%6,%7}, {%8,%9}, {%0,%1,%2,%3};\n"
                        : "+f"(acc[ma][na][0]), "+f"(acc[ma][na][1]),
                          "+f"(acc[ma][na][2]), "+f"(acc[ma][na][3])
                        : "r"(af[ma][0]), "r"(af[ma][1]), "r"(af[ma][2]), "r"(af[ma][3]),
                          "r"(bf[na][0]), "r"(bf[na][1]));
                }
        }
    }

    // epilogue
    #pragma unroll
    for (int ma = 0; ma < 4; ma++) {
        int r0 = m0 + wm * 64 + ma * 16 + g;
        #pragma unroll
        for (int na = 0; na < 4; na++) {
            int c0 = n0 + wn * 32 + na * 8 + tg * 2;
            float v0 = acc[ma][na][0], v1 = acc[ma][na][1];
            float v2 = acc[ma][na][2], v3 = acc[ma][na][3];
            if (MODE == 2) {
                float bz0 = __ldg(&bias[c0]), bz1 = __ldg(&bias[c0 + 1]);
                v0 = __uint_as_float(f2tf(fmaxf(v0 + bz0, 0.f)));
                v1 = __uint_as_float(f2tf(fmaxf(v1 + bz1, 0.f)));
                v2 = __uint_as_float(f2tf(fmaxf(v2 + bz0, 0.f)));
                v3 = __uint_as_float(f2tf(fmaxf(v3 + bz1, 0.f)));
            }
            *(float2*)&C[(size_t)r0 * N + c0]       = make_float2(v0, v1);
            *(float2*)&C[(size_t)(r0 + 8) * N + c0] = make_float2(v2, v3);
        }
    }
}

// ---------------- flag reset ----------------
__global__ void reset_flags_kernel() {
    g_ready[threadIdx.x] = 0u;
}

// ---------------- Persistent RNN recurrence ----------------
// h_t = tanh(xp_t + W_hh h_{t-1} + b_hh), 512 sequential steps, 128 CTAs.
// W_hh slice held in REGISTERS across all steps; h via __ldcg.
__global__ __launch_bounds__(256, 1) void rnn_recurrence_kernel(
        const float* __restrict__ xp,
        const float* __restrict__ Whh,
        const float* __restrict__ bhh,
        float* __restrict__ hout) {
    __shared__ float h_s[BB][HH];       // 32 KB
    __shared__ float part[2][8][BB];

    const int tid = threadIdx.x;
    const int warp = tid >> 5, lane = tid & 31;
    const int rp = warp >> 1;           // row pair 0..3
    const int fh = warp & 1;            // feature half
    const int r0 = blockIdx.x * 8 + rp * 2;

    float4 W0[4], W1[4];
    #pragma unroll
    for (int it = 0; it < 4; it++) {
        int f = fh * 512 + it * 128 + lane * 4;
        W0[it] = *(const float4*)&Whh[(size_t)r0 * HH + f];
        W1[it] = *(const float4*)&Whh[(size_t)(r0 + 1) * HH + f];
    }

    for (int t = 0; t < TT; t++) {
        #pragma unroll
        for (int i = 0; i < 8; i++) {
            int idx = tid + i * 256;
            float4 v;
            if (t == 0) {
                v = make_float4(0.f, 0.f, 0.f, 0.f);
            } else {
                int b = idx >> 8, f4 = idx & 255;
                v = __ldcg((const float4*)&hout[((size_t)(b * TT + t - 1) << 10) + (f4 << 2)]);
            }
            ((float4*)h_s)[idx] = v;
        }
        __syncthreads();

        float acc0[BB], acc1[BB];
        #pragma unroll
        for (int b = 0; b < BB; b++) { acc0[b] = 0.f; acc1[b] = 0.f; }
        #pragma unroll
        for (int it = 0; it < 4; it++) {
            int f = fh * 512 + it * 128 + lane * 4;
            float4 w0 = W0[it], w1 = W1[it];
            #pragma unroll
            for (int b = 0; b < BB; b++) {
                float4 h4 = *(const float4*)&h_s[b][f];
                acc0[b] += w0.x * h4.x + w0.y * h4.y + w0.z * h4.z + w0.w * h4.w;
                acc1[b] += w1.x * h4.x + w1.y * h4.y + w1.z * h4.z + w1.w * h4.w;
            }
        }
        #pragma unroll
        for (int off = 16; off > 0; off >>= 1) {
            #pragma unroll
            for (int b = 0; b < BB; b++) {
                acc0[b] += __shfl_xor_sync(0xffffffffu, acc0[b], off);
                acc1[b] += __shfl_xor_sync(0xffffffffu, acc1[b], off);
            }
        }
        if (lane == 0) {
            #pragma unroll
            for (int b = 0; b < BB; b++) {
                part[fh][rp * 2][b] = acc0[b];
                part[fh][rp * 2 + 1][b] = acc1[b];
            }
        }
        __syncthreads();

        if (tid < 64) {
            int lrow = tid >> 3, b = tid & 7;
            int rg = blockIdx.x * 8 + lrow;
            float v = part[0][lrow][b] + part[1][lrow][b]
                    + xp[((size_t)(b * TT + t) << 10) + rg] + bhh[rg];
            hout[((size_t)(b * TT + t) << 10) + rg] = tanhf(v);
            __threadfence();
        }
        __syncthreads();

        if (tid == 0) g_ready[blockIdx.x] = (unsigned)(t + 1);
        if (tid < RNN_NBLK) {
            while (g_ready[tid] < (unsigned)(t + 1)) { }
            __threadfence();
        }
        __syncthreads();
    }
}

// ---------------- launch ----------------
extern "C" void kernel_launch(void* const* d_in, const int* in_sizes, int n_in,
                              void* d_out, int out_size) {
    const int*   x      = (const int*)d_in[0];
    const float* emb    = (const float*)d_in[1];
    const float* W_ih0  = (const float*)d_in[2];
    const float* W_hh0  = (const float*)d_in[3];
    const float* b_ih0  = (const float*)d_in[4];
    const float* b_hh0  = (const float*)d_in[5];
    const float* W_ih1  = (const float*)d_in[6];
    const float* W_hh1  = (const float*)d_in[7];
    const float* b_ih1  = (const float*)d_in[8];
    const float* b_hh1  = (const float*)d_in[9];
    const float* W_lin  = (const float*)d_in[10];
    const float* b_lin  = (const float*)d_in[11];
    float* out = (float*)d_out;

    float *xnorm, *xp, *h0, *h1, *act, *embr, *wlr;
    cudaGetSymbolAddress((void**)&xnorm, g_xnorm);
    cudaGetSymbolAddress((void**)&xp,    g_xp);
    cudaGetSymbolAddress((void**)&h0,    g_h0);
    cudaGetSymbolAddress((void**)&h1,    g_h1);
    cudaGetSymbolAddress((void**)&act,   g_act);
    cudaGetSymbolAddress((void**)&embr,  g_embr);
    cudaGetSymbolAddress((void**)&wlr,   g_wlr);

    cudaFuncSetAttribute(tf32v2_kernel<0>, cudaFuncAttributeMaxDynamicSharedMemorySize, V2_SMEM);
    cudaFuncSetAttribute(tf32v2_kernel<2>, cudaFuncAttributeMaxDynamicSharedMemorySize, V2_SMEM);

    // 0. pre-round emb for the logits GEMM (independent; do first)
    tf32round_kernel<<<(VV * EE / 4 + 255) / 256, 256>>>(emb, embr, VV * EE / 4);
    // and W_lin for the act GEMM
    tf32round_kernel<<<(EE * HH / 4 + 255) / 256, 256>>>(W_lin, wlr, EE * HH / 4);

    // 1. xnorm = LN(emb[x])
    ln_embed_kernel<<<MTOK, 256>>>(x, emb, xnorm);

    // 2. xp = xnorm @ W_ih0^T + b_ih0   (fp32)
    {
        dim3 grid(MTOK / 128, HH / 128);
        sgemm_tn_kernel<1><<<grid, 256>>>(xnorm, W_ih0, b_ih0, xp, MTOK, HH, EE);
    }

    // 3. layer 0 recurrence
    reset_flags_kernel<<<1, RNN_NBLK>>>();
    rnn_recurrence_kernel<<<RNN_NBLK, 256>>>(xp, W_hh0, b_hh0, h0);

    // 4. xp = h0 @ W_ih1^T + b_ih1   (fp32)
    {
        dim3 grid(MTOK / 128, HH / 128);
        sgemm_tn_kernel<1><<<grid, 256>>>(h0, W_ih1, b_ih1, xp, MTOK, HH, HH);
    }

    // 5. layer 1 recurrence
    reset_flags_kernel<<<1, RNN_NBLK>>>();
    rnn_recurrence_kernel<<<RNN_NBLK, 256>>>(xp, W_hh1, b_hh1, h1);

    // 5b. round h1 into xnorm (free scratch)
    tf32round_kernel<<<(MTOK * HH / 4 + 255) / 256, 256>>>(h1, xnorm, MTOK * HH / 4);

    // 6. act = relu(h1r @ wlr^T + b_lin), rounded on store  (tf32 mma v2)
    {
        dim3 grid(MTOK / 256, EE / 128);
        tf32v2_kernel<2><<<grid, 512, V2_SMEM>>>(xnorm, wlr, b_lin, act, EE);
    }

    // 7. out = act @ embr^T   [4096, 32000]  (tf32 mma v2)
    {
        dim3 grid(MTOK / 256, VV / 128);
        tf32v2_kernel<0><<<grid, 512, V2_SMEM>>>(act, embr, nullptr, out, VV);
    }
}

// round 6
// speedup vs baseline: 1.1404x; 1.1404x over previous
#include <cuda_runtime.h>
#include <cuda_fp16.h>
#include <math.h>
#include <stdint.h>

#define VV 32000
#define EE 1024
#define HH 1024
#define BB 8
#define TT 512
#define MTOK 4096   // B*T
#define GK 1024     // K for both tensor GEMMs
#define NKCH 32     // K chunks of 32

#define RNN_NBLK 128

// ---------------- scratch (device globals; no allocation) ----------------
__device__ float  g_xp[MTOK * HH];
__device__ float  g_h0[MTOK * HH];
__device__ float  g_h1[MTOK * HH];
__device__ float  g_xnorm[MTOK * EE];
__device__ __half g_embh[VV * EE];     // fp16 emb (65 MB)
__device__ __half g_wlh[EE * HH];      // fp16 W_lin
__device__ __half g_h1h[MTOK * HH];    // fp16 h1
__device__ __half g_acth[MTOK * EE];   // fp16 act (logits A operand)

__device__ volatile unsigned g_ready[RNN_NBLK];

// ---------------- helpers ----------------
__device__ __forceinline__ uint32_t smem_u32(const void* p) {
    uint32_t a;
    asm("{ .reg .u64 t; cvta.to.shared.u64 t, %1; cvt.u32.u64 %0, t; }"
        : "=r"(a) : "l"(p));
    return a;
}
__device__ __forceinline__ void cp16(uint32_t d, const void* s) {
    asm volatile("cp.async.cg.shared.global [%0], [%1], 16;" :: "r"(d), "l"(s));
}
#define CP_COMMIT() asm volatile("cp.async.commit_group;" ::: "memory")
#define CP_WAIT(n)  asm volatile("cp.async.wait_group %0;" :: "n"(n) : "memory")

__device__ __forceinline__ void ldm4(unsigned r[4], uint32_t addr) {
    asm volatile("ldmatrix.sync.aligned.m8n8.x4.shared.b16 {%0,%1,%2,%3}, [%4];"
                 : "=r"(r[0]), "=r"(r[1]), "=r"(r[2]), "=r"(r[3]) : "r"(addr));
}

// ---------------- LayerNorm(emb[x]) ----------------
__global__ void ln_embed_kernel(const int* __restrict__ x,
                                const float* __restrict__ emb,
                                float* __restrict__ out) {
    int r = blockIdx.x;
    int tid = threadIdx.x;               // 256 threads
    int row = x[r];
    const float4* src = (const float4*)(emb + (size_t)row * EE);
    float4 v = src[tid];
    float s = v.x + v.y + v.z + v.w;
    float q = v.x * v.x + v.y * v.y + v.z * v.z + v.w * v.w;
    #pragma unroll
    for (int off = 16; off > 0; off >>= 1) {
        s += __shfl_xor_sync(0xffffffffu, s, off);
        q += __shfl_xor_sync(0xffffffffu, q, off);
    }
    __shared__ float sh_s[8], sh_q[8];
    int warp = tid >> 5, lane = tid & 31;
    if (lane == 0) { sh_s[warp] = s; sh_q[warp] = q; }
    __syncthreads();
    __shared__ float s_mu, s_inv;
    if (tid == 0) {
        float S = 0.f, Q = 0.f;
        #pragma unroll
        for (int i = 0; i < 8; i++) { S += sh_s[i]; Q += sh_q[i]; }
        float mu = S * (1.0f / EE);
        float var = Q * (1.0f / EE) - mu * mu;
        s_mu = mu;
        s_inv = rsqrtf(var + 1e-5f);
    }
    __syncthreads();
    float mu = s_mu, inv = s_inv;
    float4 o;
    o.x = (v.x - mu) * inv; o.y = (v.y - mu) * inv;
    o.z = (v.z - mu) * inv; o.w = (v.w - mu) * inv;
    ((float4*)(out + (size_t)r * EE))[tid] = o;
}

// ---------------- fp32 -> fp16 conversion ----------------
__global__ void f2h_kernel(const float* __restrict__ src,
                           __half* __restrict__ dst, int n4) {
    int i = blockIdx.x * blockDim.x + threadIdx.x;
    if (i < n4) {
        float4 v = ((const float4*)src)[i];
        __half2 h0 = __floats2half2_rn(v.x, v.y);
        __half2 h1 = __floats2half2_rn(v.z, v.w);
        uint2 o;
        o.x = *(unsigned*)&h0;
        o.y = *(unsigned*)&h1;
        ((uint2*)dst)[i] = o;
    }
}

// ---------------- fp32 SGEMM (recurrence-feeding projections) ----------------
template <int MODE>  // 1: +bias
__global__ void sgemm_tn_kernel(const float* __restrict__ A,
                                const float* __restrict__ B,
                                const float* __restrict__ bias,
                                float* __restrict__ C,
                                int M, int N, int K) {
    __shared__ float As[16][132];
    __shared__ float Bs[16][132];

    const int tid = threadIdx.x;
    const int m0 = blockIdx.x * 128;
    const int n0 = blockIdx.y * 128;
    const int tx = tid & 15;
    const int ty = tid >> 4;
    const int lr = tid >> 2;
    const int lk = (tid & 3) * 4;

    float c[8][8];
    #pragma unroll
    for (int i = 0; i < 8; i++)
        #pragma unroll
        for (int j = 0; j < 8; j++) c[i][j] = 0.f;

    for (int kt = 0; kt < K; kt += 16) {
        __syncthreads();
        float4 a0 = *(const float4*)&A[(size_t)(m0 + lr) * K + kt + lk];
        float4 a1 = *(const float4*)&A[(size_t)(m0 + lr + 64) * K + kt + lk];
        float4 b0 = *(const float4*)&B[(size_t)(n0 + lr) * K + kt + lk];
        float4 b1 = *(const float4*)&B[(size_t)(n0 + lr + 64) * K + kt + lk];
        As[lk + 0][lr] = a0.x; As[lk + 1][lr] = a0.y; As[lk + 2][lr] = a0.z; As[lk + 3][lr] = a0.w;
        As[lk + 0][lr + 64] = a1.x; As[lk + 1][lr + 64] = a1.y; As[lk + 2][lr + 64] = a1.z; As[lk + 3][lr + 64] = a1.w;
        Bs[lk + 0][lr] = b0.x; Bs[lk + 1][lr] = b0.y; Bs[lk + 2][lr] = b0.z; Bs[lk + 3][lr] = b0.w;
        Bs[lk + 0][lr + 64] = b1.x; Bs[lk + 1][lr + 64] = b1.y; Bs[lk + 2][lr + 64] = b1.z; Bs[lk + 3][lr + 64] = b1.w;
        __syncthreads();
        #pragma unroll
        for (int k = 0; k < 16; k++) {
            float4 aA = *(const float4*)&As[k][ty * 8];
            float4 aB = *(const float4*)&As[k][ty * 8 + 4];
            float4 bA = *(const float4*)&Bs[k][tx * 8];
            float4 bB = *(const float4*)&Bs[k][tx * 8 + 4];
            float a[8] = {aA.x, aA.y, aA.z, aA.w, aB.x, aB.y, aB.z, aB.w};
            float b[8] = {bA.x, bA.y, bA.z, bA.w, bB.x, bB.y, bB.z, bB.w};
            #pragma unroll
            for (int i = 0; i < 8; i++)
                #pragma unroll
                for (int j = 0; j < 8; j++)
                    c[i][j] = fmaf(a[i], b[j], c[i][j]);
        }
    }

    float bb0[8];
    if (MODE != 0) {
        float4 t0 = *(const float4*)&bias[n0 + tx * 8];
        float4 t1 = *(const float4*)&bias[n0 + tx * 8 + 4];
        bb0[0] = t0.x; bb0[1] = t0.y; bb0[2] = t0.z; bb0[3] = t0.w;
        bb0[4] = t1.x; bb0[5] = t1.y; bb0[6] = t1.z; bb0[7] = t1.w;
    }

    #pragma unroll
    for (int i = 0; i < 8; i++) {
        int row = m0 + ty * 8 + i;
        float o[8];
        #pragma unroll
        for (int j = 0; j < 8; j++) {
            float v = c[i][j];
            if (MODE != 0) v += bb0[j];
            o[j] = v;
        }
        *(float4*)&C[(size_t)row * N + n0 + tx * 8] = make_float4(o[0], o[1], o[2], o[3]);
        *(float4*)&C[(size_t)row * N + n0 + tx * 8 + 4] = make_float4(o[4], o[5], o[6], o[7]);
    }
}

// ---------------- fp16 HMMA GEMM: C[M,N] = A[M,K] * B[N,K]^T ----------------
// A, B are fp16. BM=256, BN=128, BK=32, 512 threads (4Mx4N warps, 64x32 tiles).
// 4-stage cp.async pipeline. smem rows = 64B (32 fp16), swizzle c ^= (row>>1)&3.
// MODE 0: float C, plain.  MODE 2: half C, relu(x+bias).
#define H_ABYTES (256 * 64)          // 16384
#define H_BBYTES (128 * 64)          // 8192
#define H_STAGE  (H_ABYTES + H_BBYTES)
#define H_STAGES 4
#define H_SMEM   (H_STAGES * H_STAGE)   // 98304

template <int MODE>
__global__ __launch_bounds__(512) void hgemm_tn_kernel(
        const __half* __restrict__ A,
        const __half* __restrict__ Bm,
        const float* __restrict__ bias,
        void* __restrict__ Cv,
        int N) {
    extern __shared__ char smem[];
    const uint32_t sb = smem_u32(smem);

    const int tid  = threadIdx.x;
    const int lane = tid & 31;
    const int warp = tid >> 5;
    const int g    = lane >> 2;
    const int tg   = lane & 3;
    const int wm   = warp & 3;     // M quadrant (64 rows)
    const int wn   = warp >> 2;    // N quadrant (32 cols)
    const int m0 = blockIdx.x * 256;
    const int n0 = blockIdx.y * 128;

    const int li = lane & 7;       // ldmatrix lane row
    const int lq = lane >> 3;      // ldmatrix quadrant

    float acc[4][4][4];
    #pragma unroll
    for (int i = 0; i < 4; i++)
        #pragma unroll
        for (int j = 0; j < 4; j++)
            #pragma unroll
            for (int q = 0; q < 4; q++) acc[i][j][q] = 0.f;

    // ---- async copy of one stage (A: 1024 chunks, B: 512 chunks of 16B) ----
    auto issue = [&](int st, int kt) {
        uint32_t ab = sb + st * H_STAGE;
        uint32_t bb = ab + H_ABYTES;
        #pragma unroll
        for (int i = 0; i < 2; i++) {
            int idx = tid + i * 512;
            int row = idx >> 2, c = idx & 3;
            int sw = c ^ ((row >> 1) & 3);
            cp16(ab + row * 64 + sw * 16, &A[(size_t)(m0 + row) * GK + kt + c * 8]);
        }
        {
            int row = tid >> 2, c = tid & 3;
            int sw = c ^ ((row >> 1) & 3);
            cp16(bb + row * 64 + sw * 16, &Bm[(size_t)(n0 + row) * GK + kt + c * 8]);
        }
        CP_COMMIT();
    };

    #pragma unroll
    for (int s = 0; s < H_STAGES - 1; s++) issue(s, s * 32);

    for (int ci = 0; ci < NKCH; ci++) {
        CP_WAIT(H_STAGES - 2);
        __syncthreads();
        if (ci + H_STAGES - 1 < NKCH)
            issue((ci + H_STAGES - 1) % H_STAGES, (ci + H_STAGES - 1) * 32);

        uint32_t ab = sb + (ci % H_STAGES) * H_STAGE;
        uint32_t bb = ab + H_ABYTES;

        #pragma unroll
        for (int kk = 0; kk < 2; kk++) {           // two k16 steps per k32
            // A fragments: 4 ldmatrix.x4 (one per 16-row group)
            unsigned af[4][4];
            #pragma unroll
            for (int ma = 0; ma < 4; ma++) {
                int row = wm * 64 + ma * 16 + (lq & 1) * 8 + li;
                int ch  = kk * 2 + (lq >> 1);
                uint32_t ad = ab + row * 64 + ((ch ^ ((row >> 1) & 3)) * 16);
                ldm4(af[ma], ad);
            }
            // B fragments: 2 ldmatrix.x4 (one per 16-col group)
            unsigned bf[2][4];
            #pragma unroll
            for (int ng = 0; ng < 2; ng++) {
                int row = wn * 32 + ng * 16 + (lq >> 1) * 8 + li;
                int ch  = kk * 2 + (lq & 1);
                uint32_t bd = bb + row * 64 + ((ch ^ ((row >> 1) & 3)) * 16);
                ldm4(bf[ng], bd);
            }
            #pragma unroll
            for (int ma = 0; ma < 4; ma++)
                #pragma unroll
                for (int na = 0; na < 4; na++) {
                    const unsigned b0 = bf[na >> 1][(na & 1) * 2 + 0];
                    const unsigned b1 = bf[na >> 1][(na & 1) * 2 + 1];
                    asm volatile(
                        "mma.sync.aligned.m16n8k16.row.col.f32.f16.f16.f32 "
                        "{%0,%1,%2,%3}, {%4,%5,%6,%7}, {%8,%9}, {%0,%1,%2,%3};\n"
                        : "+f"(acc[ma][na][0]), "+f"(acc[ma][na][1]),
                          "+f"(acc[ma][na][2]), "+f"(acc[ma][na][3])
                        : "r"(af[ma][0]), "r"(af[ma][1]), "r"(af[ma][2]), "r"(af[ma][3]),
                          "r"(b0), "r"(b1));
                }
        }
    }

    // epilogue
    #pragma unroll
    for (int ma = 0; ma < 4; ma++) {
        int r0 = m0 + wm * 64 + ma * 16 + g;
        #pragma unroll
        for (int na = 0; na < 4; na++) {
            int c0 = n0 + wn * 32 + na * 8 + tg * 2;
            float v0 = acc[ma][na][0], v1 = acc[ma][na][1];
            float v2 = acc[ma][na][2], v3 = acc[ma][na][3];
            if (MODE == 2) {
                __half* C = (__half*)Cv;
                float bz0 = __ldg(&bias[c0]), bz1 = __ldg(&bias[c0 + 1]);
                __half2 h0 = __floats2half2_rn(fmaxf(v0 + bz0, 0.f), fmaxf(v1 + bz1, 0.f));
                __half2 h2 = __floats2half2_rn(fmaxf(v2 + bz0, 0.f), fmaxf(v3 + bz1, 0.f));
                *(__half2*)&C[(size_t)r0 * N + c0]       = h0;
                *(__half2*)&C[(size_t)(r0 + 8) * N + c0] = h2;
            } else {
                float* C = (float*)Cv;
                *(float2*)&C[(size_t)r0 * N + c0]       = make_float2(v0, v1);
                *(float2*)&C[(size_t)(r0 + 8) * N + c0] = make_float2(v2, v3);
            }
        }
    }
}

// ---------------- flag reset ----------------
__global__ void reset_flags_kernel() {
    g_ready[threadIdx.x] = 0u;
}

// ---------------- Persistent RNN recurrence ----------------
__global__ __launch_bounds__(256, 1) void rnn_recurrence_kernel(
        const float* __restrict__ xp,
        const float* __restrict__ Whh,
        const float* __restrict__ bhh,
        float* __restrict__ hout) {
    __shared__ float h_s[BB][HH];       // 32 KB
    __shared__ float part[2][8][BB];

    const int tid = threadIdx.x;
    const int warp = tid >> 5, lane = tid & 31;
    const int rp = warp >> 1;           // row pair 0..3
    const int fh = warp & 1;            // feature half
    const int r0 = blockIdx.x * 8 + rp * 2;

    float4 W0[4], W1[4];
    #pragma unroll
    for (int it = 0; it < 4; it++) {
        int f = fh * 512 + it * 128 + lane * 4;
        W0[it] = *(const float4*)&Whh[(size_t)r0 * HH + f];
        W1[it] = *(const float4*)&Whh[(size_t)(r0 + 1) * HH + f];
    }

    for (int t = 0; t < TT; t++) {
        #pragma unroll
        for (int i = 0; i < 8; i++) {
            int idx = tid + i * 256;
            float4 v;
            if (t == 0) {
                v = make_float4(0.f, 0.f, 0.f, 0.f);
            } else {
                int b = idx >> 8, f4 = idx & 255;
                v = __ldcg((const float4*)&hout[((size_t)(b * TT + t - 1) << 10) + (f4 << 2)]);
            }
            ((float4*)h_s)[idx] = v;
        }
        __syncthreads();

        float acc0[BB], acc1[BB];
        #pragma unroll
        for (int b = 0; b < BB; b++) { acc0[b] = 0.f; acc1[b] = 0.f; }
        #pragma unroll
        for (int it = 0; it < 4; it++) {
            int f = fh * 512 + it * 128 + lane * 4;
            float4 w0 = W0[it], w1 = W1[it];
            #pragma unroll
            for (int b = 0; b < BB; b++) {
                float4 h4 = *(const float4*)&h_s[b][f];
                acc0[b] += w0.x * h4.x + w0.y * h4.y + w0.z * h4.z + w0.w * h4.w;
                acc1[b] += w1.x * h4.x + w1.y * h4.y + w1.z * h4.z + w1.w * h4.w;
            }
        }
        #pragma unroll
        for (int off = 16; off > 0; off >>= 1) {
            #pragma unroll
            for (int b = 0; b < BB; b++) {
                acc0[b] += __shfl_xor_sync(0xffffffffu, acc0[b], off);
                acc1[b] += __shfl_xor_sync(0xffffffffu, acc1[b], off);
            }
        }
        if (lane == 0) {
            #pragma unroll
            for (int b = 0; b < BB; b++) {
                part[fh][rp * 2][b] = acc0[b];
                part[fh][rp * 2 + 1][b] = acc1[b];
            }
        }
        __syncthreads();

        if (tid < 64) {
            int lrow = tid >> 3, b = tid & 7;
            int rg = blockIdx.x * 8 + lrow;
            float v = part[0][lrow][b] + part[1][lrow][b]
                    + xp[((size_t)(b * TT + t) << 10) + rg] + bhh[rg];
            hout[((size_t)(b * TT + t) << 10) + rg] = tanhf(v);
            __threadfence();
        }
        __syncthreads();

        if (tid == 0) g_ready[blockIdx.x] = (unsigned)(t + 1);
        if (tid < RNN_NBLK) {
            while (g_ready[tid] < (unsigned)(t + 1)) { }
            __threadfence();
        }
        __syncthreads();
    }
}

// ---------------- launch ----------------
extern "C" void kernel_launch(void* const* d_in, const int* in_sizes, int n_in,
                              void* d_out, int out_size) {
    const int*   x      = (const int*)d_in[0];
    const float* emb    = (const float*)d_in[1];
    const float* W_ih0  = (const float*)d_in[2];
    const float* W_hh0  = (const float*)d_in[3];
    const float* b_ih0  = (const float*)d_in[4];
    const float* b_hh0  = (const float*)d_in[5];
    const float* W_ih1  = (const float*)d_in[6];
    const float* W_hh1  = (const float*)d_in[7];
    const float* b_ih1  = (const float*)d_in[8];
    const float* b_hh1  = (const float*)d_in[9];
    const float* W_lin  = (const float*)d_in[10];
    const float* b_lin  = (const float*)d_in[11];
    float* out = (float*)d_out;

    float *xnorm, *xp, *h0, *h1;
    __half *embh, *wlh, *h1h, *acth;
    cudaGetSymbolAddress((void**)&xnorm, g_xnorm);
    cudaGetSymbolAddress((void**)&xp,    g_xp);
    cudaGetSymbolAddress((void**)&h0,    g_h0);
    cudaGetSymbolAddress((void**)&h1,    g_h1);
    cudaGetSymbolAddress((void**)&embh,  g_embh);
    cudaGetSymbolAddress((void**)&wlh,   g_wlh);
    cudaGetSymbolAddress((void**)&h1h,   g_h1h);
    cudaGetSymbolAddress((void**)&acth,  g_acth);

    cudaFuncSetAttribute(hgemm_tn_kernel<0>, cudaFuncAttributeMaxDynamicSharedMemorySize, H_SMEM);
    cudaFuncSetAttribute(hgemm_tn_kernel<2>, cudaFuncAttributeMaxDynamicSharedMemorySize, H_SMEM);

    // 0. fp16 conversions needed later (independent of the sequential chain)
    f2h_kernel<<<(VV * EE / 4 + 255) / 256, 256>>>(emb, embh, VV * EE / 4);
    f2h_kernel<<<(EE * HH / 4 + 255) / 256, 256>>>(W_lin, wlh, EE * HH / 4);

    // 1. xnorm = LN(emb[x])
    ln_embed_kernel<<<MTOK, 256>>>(x, emb, xnorm);

    // 2. xp = xnorm @ W_ih0^T + b_ih0   (fp32)
    {
        dim3 grid(MTOK / 128, HH / 128);
        sgemm_tn_kernel<1><<<grid, 256>>>(xnorm, W_ih0, b_ih0, xp, MTOK, HH, EE);
    }

    // 3. layer 0 recurrence
    reset_flags_kernel<<<1, RNN_NBLK>>>();
    rnn_recurrence_kernel<<<RNN_NBLK, 256>>>(xp, W_hh0, b_hh0, h0);

    // 4. xp = h0 @ W_ih1^T + b_ih1   (fp32)
    {
        dim3 grid(MTOK / 128, HH / 128);
        sgemm_tn_kernel<1><<<grid, 256>>>(h0, W_ih1, b_ih1, xp, MTOK, HH, HH);
    }

    // 5. layer 1 recurrence
    reset_flags_kernel<<<1, RNN_NBLK>>>();
    rnn_recurrence_kernel<<<RNN_NBLK, 256>>>(xp, W_hh1, b_hh1, h1);

    // 5b. h1 -> fp16
    f2h_kernel<<<(MTOK * HH / 4 + 255) / 256, 256>>>(h1, h1h, MTOK * HH / 4);

    // 6. acth = relu(h1h @ wlh^T + b_lin)   (fp16 HMMA, fp16 out)
    {
        dim3 grid(MTOK / 256, EE / 128);
        hgemm_tn_kernel<2><<<grid, 512, H_SMEM>>>(h1h, wlh, b_lin, acth, EE);
    }

    // 7. out = acth @ embh^T   [4096, 32000]  (fp16 HMMA, fp32 out)
    {
        dim3 grid(MTOK / 256, VV / 128);
        hgemm_tn_kernel<0><<<grid, 512, H_SMEM>>>(acth, embh, nullptr, out, VV);
    }
}

// round 7
// speedup vs baseline: 1.6712x; 1.4654x over previous
#include <cuda_runtime.h>
#include <cuda_fp16.h>
#include <math.h>
#include <stdint.h>

#define VV 32000
#define EE 1024
#define HH 1024
#define BB 8
#define TT 512
#define MTOK 4096   // B*T
#define GK 1024     // K for tensor GEMMs
#define NKCH 32     // K chunks of 32

#define RNN_NBLK 128

// ---------------- scratch (device globals; no allocation) ----------------
__device__ float  g_xp[MTOK * HH];
__device__ float  g_h0[MTOK * HH];
__device__ float  g_h1[MTOK * HH];
__device__ float  g_xnorm[MTOK * EE];
__device__ __half g_embh[VV * EE];     // fp16 emb (65 MB)
__device__ __half g_wlh[EE * HH];      // fp16 W_lin
__device__ __half g_h1h[MTOK * HH];    // fp16 h1
__device__ __half g_acth[MTOK * EE];   // fp16 act (logits A operand)

__device__ volatile unsigned g_ready[RNN_NBLK];
__device__ volatile unsigned g_master;

// ---------------- helpers ----------------
__device__ __forceinline__ uint32_t smem_u32(const void* p) {
    uint32_t a;
    asm("{ .reg .u64 t; cvta.to.shared.u64 t, %1; cvt.u32.u64 %0, t; }"
        : "=r"(a) : "l"(p));
    return a;
}
__device__ __forceinline__ void cp16(uint32_t d, const void* s) {
    asm volatile("cp.async.cg.shared.global [%0], [%1], 16;" :: "r"(d), "l"(s));
}
#define CP_COMMIT() asm volatile("cp.async.commit_group;" ::: "memory")
#define CP_WAIT(n)  asm volatile("cp.async.wait_group %0;" :: "n"(n) : "memory")

__device__ __forceinline__ void ldm4(unsigned r[4], uint32_t addr) {
    asm volatile("ldmatrix.sync.aligned.m8n8.x4.shared.b16 {%0,%1,%2,%3}, [%4];"
                 : "=r"(r[0]), "=r"(r[1]), "=r"(r[2]), "=r"(r[3]) : "r"(addr));
}

// packed f32x2 ops (sm_100+ family)
__device__ __forceinline__ unsigned long long packf2(float lo, float hi) {
    unsigned long long p;
    asm("mov.b64 %0, {%1, %2};" : "=l"(p) : "f"(lo), "f"(hi));
    return p;
}
__device__ __forceinline__ void unpackf2(float& lo, float& hi, unsigned long long p) {
    asm("mov.b64 {%0, %1}, %2;" : "=f"(lo), "=f"(hi) : "l"(p));
}
__device__ __forceinline__ void fma2(unsigned long long& c,
                                     unsigned long long a, unsigned long long b) {
    asm("fma.rn.f32x2 %0, %1, %2, %0;" : "+l"(c) : "l"(a), "l"(b));
}

// ---------------- LayerNorm(emb[x]) ----------------
__global__ void ln_embed_kernel(const int* __restrict__ x,
                                const float* __restrict__ emb,
                                float* __restrict__ out) {
    int r = blockIdx.x;
    int tid = threadIdx.x;               // 256 threads
    int row = x[r];
    const float4* src = (const float4*)(emb + (size_t)row * EE);
    float4 v = src[tid];
    float s = v.x + v.y + v.z + v.w;
    float q = v.x * v.x + v.y * v.y + v.z * v.z + v.w * v.w;
    #pragma unroll
    for (int off = 16; off > 0; off >>= 1) {
        s += __shfl_xor_sync(0xffffffffu, s, off);
        q += __shfl_xor_sync(0xffffffffu, q, off);
    }
    __shared__ float sh_s[8], sh_q[8];
    int warp = tid >> 5, lane = tid & 31;
    if (lane == 0) { sh_s[warp] = s; sh_q[warp] = q; }
    __syncthreads();
    __shared__ float s_mu, s_inv;
    if (tid == 0) {
        float S = 0.f, Q = 0.f;
        #pragma unroll
        for (int i = 0; i < 8; i++) { S += sh_s[i]; Q += sh_q[i]; }
        float mu = S * (1.0f / EE);
        float var = Q * (1.0f / EE) - mu * mu;
        s_mu = mu;
        s_inv = rsqrtf(var + 1e-5f);
    }
    __syncthreads();
    float mu = s_mu, inv = s_inv;
    float4 o;
    o.x = (v.x - mu) * inv; o.y = (v.y - mu) * inv;
    o.z = (v.z - mu) * inv; o.w = (v.w - mu) * inv;
    ((float4*)(out + (size_t)r * EE))[tid] = o;
}

// ---------------- fp32 -> fp16 conversion ----------------
__global__ void f2h_kernel(const float* __restrict__ src,
                           __half* __restrict__ dst, int n4) {
    int i = blockIdx.x * blockDim.x + threadIdx.x;
    if (i < n4) {
        float4 v = ((const float4*)src)[i];
        __half2 h0 = __floats2half2_rn(v.x, v.y);
        __half2 h1 = __floats2half2_rn(v.z, v.w);
        uint2 o;
        o.x = *(unsigned*)&h0;
        o.y = *(unsigned*)&h1;
        ((uint2*)dst)[i] = o;
    }
}

// ---------------- fp32 SGEMM with packed f32x2 FMA ----------------
// C[M,N] = A[M,K] * B[N,K]^T (+bias). Results bit-identical to scalar fp32.
template <int MODE>  // 1: +bias
__global__ void sgemm_tn_kernel(const float* __restrict__ A,
                                const float* __restrict__ B,
                                const float* __restrict__ bias,
                                float* __restrict__ C,
                                int M, int N, int K) {
    __shared__ float As[16][132];
    __shared__ float Bs[16][132];

    const int tid = threadIdx.x;
    const int m0 = blockIdx.x * 128;
    const int n0 = blockIdx.y * 128;
    const int tx = tid & 15;
    const int ty = tid >> 4;
    const int lr = tid >> 2;
    const int lk = (tid & 3) * 4;

    unsigned long long c2[8][4];
    #pragma unroll
    for (int i = 0; i < 8; i++)
        #pragma unroll
        for (int j = 0; j < 4; j++) c2[i][j] = 0ull;

    for (int kt = 0; kt < K; kt += 16) {
        __syncthreads();
        float4 a0 = *(const float4*)&A[(size_t)(m0 + lr) * K + kt + lk];
        float4 a1 = *(const float4*)&A[(size_t)(m0 + lr + 64) * K + kt + lk];
        float4 b0 = *(const float4*)&B[(size_t)(n0 + lr) * K + kt + lk];
        float4 b1 = *(const float4*)&B[(size_t)(n0 + lr + 64) * K + kt + lk];
        As[lk + 0][lr] = a0.x; As[lk + 1][lr] = a0.y; As[lk + 2][lr] = a0.z; As[lk + 3][lr] = a0.w;
        As[lk + 0][lr + 64] = a1.x; As[lk + 1][lr + 64] = a1.y; As[lk + 2][lr + 64] = a1.z; As[lk + 3][lr + 64] = a1.w;
        Bs[lk + 0][lr] = b0.x; Bs[lk + 1][lr] = b0.y; Bs[lk + 2][lr] = b0.z; Bs[lk + 3][lr] = b0.w;
        Bs[lk + 0][lr + 64] = b1.x; Bs[lk + 1][lr + 64] = b1.y; Bs[lk + 2][lr + 64] = b1.z; Bs[lk + 3][lr + 64] = b1.w;
        __syncthreads();
        #pragma unroll
        for (int k = 0; k < 16; k++) {
            float4 aA = *(const float4*)&As[k][ty * 8];
            float4 aB = *(const float4*)&As[k][ty * 8 + 4];
            float4 bA = *(const float4*)&Bs[k][tx * 8];
            float4 bB = *(const float4*)&Bs[k][tx * 8 + 4];
            float a[8] = {aA.x, aA.y, aA.z, aA.w, aB.x, aB.y, aB.z, aB.w};
            unsigned long long pb[4];
            pb[0] = packf2(bA.x, bA.y);
            pb[1] = packf2(bA.z, bA.w);
            pb[2] = packf2(bB.x, bB.y);
            pb[3] = packf2(bB.z, bB.w);
            #pragma unroll
            for (int i = 0; i < 8; i++) {
                unsigned long long pa = packf2(a[i], a[i]);
                #pragma unroll
                for (int j = 0; j < 4; j++) fma2(c2[i][j], pa, pb[j]);
            }
        }
    }

    float bb0[8];
    if (MODE != 0) {
        float4 t0 = *(const float4*)&bias[n0 + tx * 8];
        float4 t1 = *(const float4*)&bias[n0 + tx * 8 + 4];
        bb0[0] = t0.x; bb0[1] = t0.y; bb0[2] = t0.z; bb0[3] = t0.w;
        bb0[4] = t1.x; bb0[5] = t1.y; bb0[6] = t1.z; bb0[7] = t1.w;
    }

    #pragma unroll
    for (int i = 0; i < 8; i++) {
        int row = m0 + ty * 8 + i;
        float o[8];
        #pragma unroll
        for (int j = 0; j < 4; j++) unpackf2(o[j * 2], o[j * 2 + 1], c2[i][j]);
        if (MODE != 0) {
            #pragma unroll
            for (int j = 0; j < 8; j++) o[j] += bb0[j];
        }
        *(float4*)&C[(size_t)row * N + n0 + tx * 8] = make_float4(o[0], o[1], o[2], o[3]);
        *(float4*)&C[(size_t)row * N + n0 + tx * 8 + 4] = make_float4(o[4], o[5], o[6], o[7]);
    }
}

// ---------------- fp16 HMMA GEMM: C[M,N] = A[M,K] * B[N,K]^T ----------------
// BM=256, BN=128, BK=32, 512 threads (4Mx4N warps, 64x32 tiles).
// 4-stage cp.async pipeline. smem rows = 64B, swizzle c ^= (row>>1)&3.
// MODE 0: float C, plain.  MODE 2: half C, relu(x+bias).
#define H_ABYTES (256 * 64)
#define H_BBYTES (128 * 64)
#define H_STAGE  (H_ABYTES + H_BBYTES)
#define H_STAGES 4
#define H_SMEM   (H_STAGES * H_STAGE)   // 98304

template <int MODE>
__global__ __launch_bounds__(512) void hgemm_tn_kernel(
        const __half* __restrict__ A,
        const __half* __restrict__ Bm,
        const float* __restrict__ bias,
        void* __restrict__ Cv,
        int N) {
    extern __shared__ char smem[];
    const uint32_t sb = smem_u32(smem);

    const int tid  = threadIdx.x;
    const int lane = tid & 31;
    const int warp = tid >> 5;
    const int g    = lane >> 2;
    const int tg   = lane & 3;
    const int wm   = warp & 3;
    const int wn   = warp >> 2;
    const int m0 = blockIdx.x * 256;
    const int n0 = blockIdx.y * 128;

    const int li = lane & 7;
    const int lq = lane >> 3;

    float acc[4][4][4];
    #pragma unroll
    for (int i = 0; i < 4; i++)
        #pragma unroll
        for (int j = 0; j < 4; j++)
            #pragma unroll
            for (int q = 0; q < 4; q++) acc[i][j][q] = 0.f;

    auto issue = [&](int st, int kt) {
        uint32_t ab = sb + st * H_STAGE;
        uint32_t bb = ab + H_ABYTES;
        #pragma unroll
        for (int i = 0; i < 2; i++) {
            int idx = tid + i * 512;
            int row = idx >> 2, c = idx & 3;
            int sw = c ^ ((row >> 1) & 3);
            cp16(ab + row * 64 + sw * 16, &A[(size_t)(m0 + row) * GK + kt + c * 8]);
        }
        {
            int row = tid >> 2, c = tid & 3;
            int sw = c ^ ((row >> 1) & 3);
            cp16(bb + row * 64 + sw * 16, &Bm[(size_t)(n0 + row) * GK + kt + c * 8]);
        }
        CP_COMMIT();
    };

    #pragma unroll
    for (int s = 0; s < H_STAGES - 1; s++) issue(s, s * 32);

    for (int ci = 0; ci < NKCH; ci++) {
        CP_WAIT(H_STAGES - 2);
        __syncthreads();
        if (ci + H_STAGES - 1 < NKCH)
            issue((ci + H_STAGES - 1) % H_STAGES, (ci + H_STAGES - 1) * 32);

        uint32_t ab = sb + (ci % H_STAGES) * H_STAGE;
        uint32_t bb = ab + H_ABYTES;

        #pragma unroll
        for (int kk = 0; kk < 2; kk++) {
            unsigned af[4][4];
            #pragma unroll
            for (int ma = 0; ma < 4; ma++) {
                int row = wm * 64 + ma * 16 + (lq & 1) * 8 + li;
                int ch  = kk * 2 + (lq >> 1);
                uint32_t ad = ab + row * 64 + ((ch ^ ((row >> 1) & 3)) * 16);
                ldm4(af[ma], ad);
            }
            unsigned bf[2][4];
            #pragma unroll
            for (int ng = 0; ng < 2; ng++) {
                int row = wn * 32 + ng * 16 + (lq >> 1) * 8 + li;
                int ch  = kk * 2 + (lq & 1);
                uint32_t bd = bb + row * 64 + ((ch ^ ((row >> 1) & 3)) * 16);
                ldm4(bf[ng], bd);
            }
            #pragma unroll
            for (int ma = 0; ma < 4; ma++)
                #pragma unroll
                for (int na = 0; na < 4; na++) {
                    const unsigned b0 = bf[na >> 1][(na & 1) * 2 + 0];
                    const unsigned b1 = bf[na >> 1][(na & 1) * 2 + 1];
                    asm volatile(
                        "mma.sync.aligned.m16n8k16.row.col.f32.f16.f16.f32 "
                        "{%0,%1,%2,%3}, {%4,%5,%6,%7}, {%8,%9}, {%0,%1,%2,%3};\n"
                        : "+f"(acc[ma][na][0]), "+f"(acc[ma][na][1]),
                          "+f"(acc[ma][na][2]), "+f"(acc[ma][na][3])
                        : "r"(af[ma][0]), "r"(af[ma][1]), "r"(af[ma][2]), "r"(af[ma][3]),
                          "r"(b0), "r"(b1));
                }
        }
    }

    #pragma unroll
    for (int ma = 0; ma < 4; ma++) {
        int r0 = m0 + wm * 64 + ma * 16 + g;
        #pragma unroll
        for (int na = 0; na < 4; na++) {
            int c0 = n0 + wn * 32 + na * 8 + tg * 2;
            float v0 = acc[ma][na][0], v1 = acc[ma][na][1];
            float v2 = acc[ma][na][2], v3 = acc[ma][na][3];
            if (MODE == 2) {
                __half* C = (__half*)Cv;
                float bz0 = __ldg(&bias[c0]), bz1 = __ldg(&bias[c0 + 1]);
                __half2 h0 = __floats2half2_rn(fmaxf(v0 + bz0, 0.f), fmaxf(v1 + bz1, 0.f));
                __half2 h2 = __floats2half2_rn(fmaxf(v2 + bz0, 0.f), fmaxf(v3 + bz1, 0.f));
                *(__half2*)&C[(size_t)r0 * N + c0]       = h0;
                *(__half2*)&C[(size_t)(r0 + 8) * N + c0] = h2;
            } else {
                float* C = (float*)Cv;
                *(float2*)&C[(size_t)r0 * N + c0]       = make_float2(v0, v1);
                *(float2*)&C[(size_t)(r0 + 8) * N + c0] = make_float2(v2, v3);
            }
        }
    }
}

// ---------------- flag reset ----------------
__global__ void reset_flags_kernel() {
    g_ready[threadIdx.x] = 0u;
    if (threadIdx.x == 0) g_master = 0u;
}

// ---------------- Persistent RNN recurrence ----------------
// Leader-based grid barrier: each CTA posts its flag; CTA0 aggregates and
// publishes a single master epoch; all others poll one word.
__global__ __launch_bounds__(256, 1) void rnn_recurrence_kernel(
        const float* __restrict__ xp,
        const float* __restrict__ Whh,
        const float* __restrict__ bhh,
        float* __restrict__ hout) {
    __shared__ float h_s[BB][HH];       // 32 KB
    __shared__ float part[2][8][BB];

    const int tid = threadIdx.x;
    const int warp = tid >> 5, lane = tid & 31;
    const int rp = warp >> 1;
    const int fh = warp & 1;
    const int r0 = blockIdx.x * 8 + rp * 2;

    float4 W0[4], W1[4];
    #pragma unroll
    for (int it = 0; it < 4; it++) {
        int f = fh * 512 + it * 128 + lane * 4;
        W0[it] = *(const float4*)&Whh[(size_t)r0 * HH + f];
        W1[it] = *(const float4*)&Whh[(size_t)(r0 + 1) * HH + f];
    }

    for (int t = 0; t < TT; t++) {
        #pragma unroll
        for (int i = 0; i < 8; i++) {
            int idx = tid + i * 256;
            float4 v;
            if (t == 0) {
                v = make_float4(0.f, 0.f, 0.f, 0.f);
            } else {
                int b = idx >> 8, f4 = idx & 255;
                v = __ldcg((const float4*)&hout[((size_t)(b * TT + t - 1) << 10) + (f4 << 2)]);
            }
            ((float4*)h_s)[idx] = v;
        }
        __syncthreads();

        float acc0[BB], acc1[BB];
        #pragma unroll
        for (int b = 0; b < BB; b++) { acc0[b] = 0.f; acc1[b] = 0.f; }
        #pragma unroll
        for (int it = 0; it < 4; it++) {
            int f = fh * 512 + it * 128 + lane * 4;
            float4 w0 = W0[it], w1 = W1[it];
            #pragma unroll
            for (int b = 0; b < BB; b++) {
                float4 h4 = *(const float4*)&h_s[b][f];
                acc0[b] += w0.x * h4.x + w0.y * h4.y + w0.z * h4.z + w0.w * h4.w;
                acc1[b] += w1.x * h4.x + w1.y * h4.y + w1.z * h4.z + w1.w * h4.w;
            }
        }
        #pragma unroll
        for (int off = 16; off > 0; off >>= 1) {
            #pragma unroll
            for (int b = 0; b < BB; b++) {
                acc0[b] += __shfl_xor_sync(0xffffffffu, acc0[b], off);
                acc1[b] += __shfl_xor_sync(0xffffffffu, acc1[b], off);
            }
        }
        if (lane == 0) {
            #pragma unroll
            for (int b = 0; b < BB; b++) {
                part[fh][rp * 2][b] = acc0[b];
                part[fh][rp * 2 + 1][b] = acc1[b];
            }
        }
        __syncthreads();

        if (tid < 64) {
            int lrow = tid >> 3, b = tid & 7;
            int rg = blockIdx.x * 8 + lrow;
            float v = part[0][lrow][b] + part[1][lrow][b]
                    + xp[((size_t)(b * TT + t) << 10) + rg] + bhh[rg];
            hout[((size_t)(b * TT + t) << 10) + rg] = tanhf(v);
            __threadfence();
        }
        __syncthreads();

        // ---- leader grid barrier ----
        if (tid == 0) {
            __threadfence();
            g_ready[blockIdx.x] = (unsigned)(t + 1);   // publish arrival
        }
        if (blockIdx.x == 0) {
            if (tid < RNN_NBLK) {
                while (g_ready[tid] < (unsigned)(t + 1)) { }
            }
            __threadfence();
            __syncthreads();
            if (tid == 0) g_master = (unsigned)(t + 1);
            __syncthreads();
        } else {
            if (tid == 0) {
                while (g_master < (unsigned)(t + 1)) { }
                __threadfence();
            }
            __syncthreads();
        }
    }
}

// ---------------- launch ----------------
extern "C" void kernel_launch(void* const* d_in, const int* in_sizes, int n_in,
                              void* d_out, int out_size) {
    const int*   x      = (const int*)d_in[0];
    const float* emb    = (const float*)d_in[1];
    const float* W_ih0  = (const float*)d_in[2];
    const float* W_hh0  = (const float*)d_in[3];
    const float* b_ih0  = (const float*)d_in[4];
    const float* b_hh0  = (const float*)d_in[5];
    const float* W_ih1  = (const float*)d_in[6];
    const float* W_hh1  = (const float*)d_in[7];
    const float* b_ih1  = (const float*)d_in[8];
    const float* b_hh1  = (const float*)d_in[9];
    const float* W_lin  = (const float*)d_in[10];
    const float* b_lin  = (const float*)d_in[11];
    float* out = (float*)d_out;

    float *xnorm, *xp, *h0, *h1;
    __half *embh, *wlh, *h1h, *acth;
    cudaGetSymbolAddress((void**)&xnorm, g_xnorm);
    cudaGetSymbolAddress((void**)&xp,    g_xp);
    cudaGetSymbolAddress((void**)&h0,    g_h0);
    cudaGetSymbolAddress((void**)&h1,    g_h1);
    cudaGetSymbolAddress((void**)&embh,  g_embh);
    cudaGetSymbolAddress((void**)&wlh,   g_wlh);
    cudaGetSymbolAddress((void**)&h1h,   g_h1h);
    cudaGetSymbolAddress((void**)&acth,  g_acth);

    cudaFuncSetAttribute(hgemm_tn_kernel<0>, cudaFuncAttributeMaxDynamicSharedMemorySize, H_SMEM);
    cudaFuncSetAttribute(hgemm_tn_kernel<2>, cudaFuncAttributeMaxDynamicSharedMemorySize, H_SMEM);

    // 0. fp16 conversions (independent of the sequential chain)
    f2h_kernel<<<(VV * EE / 4 + 255) / 256, 256>>>(emb, embh, VV * EE / 4);
    f2h_kernel<<<(EE * HH / 4 + 255) / 256, 256>>>(W_lin, wlh, EE * HH / 4);

    // 1. xnorm = LN(emb[x])
    ln_embed_kernel<<<MTOK, 256>>>(x, emb, xnorm);

    // 2. xp = xnorm @ W_ih0^T + b_ih0   (fp32/f32x2)
    {
        dim3 grid(MTOK / 128, HH / 128);
        sgemm_tn_kernel<1><<<grid, 256>>>(xnorm, W_ih0, b_ih0, xp, MTOK, HH, EE);
    }

    // 3. layer 0 recurrence
    reset_flags_kernel<<<1, RNN_NBLK>>>();
    rnn_recurrence_kernel<<<RNN_NBLK, 256>>>(xp, W_hh0, b_hh0, h0);

    // 4. xp = h0 @ W_ih1^T + b_ih1   (fp32/f32x2)
    {
        dim3 grid(MTOK / 128, HH / 128);
        sgemm_tn_kernel<1><<<grid, 256>>>(h0, W_ih1, b_ih1, xp, MTOK, HH, HH);
    }

    // 5. layer 1 recurrence
    reset_flags_kernel<<<1, RNN_NBLK>>>();
    rnn_recurrence_kernel<<<RNN_NBLK, 256>>>(xp, W_hh1, b_hh1, h1);

    // 5b. h1 -> fp16
    f2h_kernel<<<(MTOK * HH / 4 + 255) / 256, 256>>>(h1, h1h, MTOK * HH / 4);

    // 6. acth = relu(h1h @ wlh^T + b_lin)   (fp16 HMMA, fp16 out)
    {
        dim3 grid(MTOK / 256, EE / 128);
        hgemm_tn_kernel<2><<<grid, 512, H_SMEM>>>(h1h, wlh, b_lin, acth, EE);
    }

    // 7. out = acth @ embh^T   [4096, 32000]  (fp16 HMMA, fp32 out)
    {
        dim3 grid(MTOK / 256, VV / 128);
        hgemm_tn_kernel<0><<<grid, 512, H_SMEM>>>(acth, embh, nullptr, out, VV);
    }
}

// round 9
// speedup vs baseline: 2.6925x; 1.6111x over previous
#include <cuda_runtime.h>
#include <cuda_fp16.h>
#include <math.h>
#include <stdint.h>

#define VV 32000
#define EE 1024
#define HH 1024
#define BB 8
#define TT 512
#define MTOK 4096   // B*T
#define GK 1024     // K for tensor GEMMs
#define NKCH 32     // K chunks of 32

#define RNN_NBLK 128

// ---------------- scratch (device globals; no allocation) ----------------
__device__ float  g_xp[MTOK * HH];
__device__ float  g_h0[MTOK * HH];
__device__ float  g_h1[MTOK * HH];
__device__ float  g_xnorm[MTOK * EE];
__device__ __half g_embh[VV * EE];     // fp16 emb (65 MB)
__device__ __half g_wlh[EE * HH];      // fp16 W_lin
__device__ __half g_h1h[MTOK * HH];    // fp16 h1
__device__ __half g_acth[MTOK * EE];   // fp16 act (logits A operand)

__device__ volatile unsigned g_ready[RNN_NBLK];
__device__ volatile unsigned g_master;

// ---------------- helpers ----------------
__device__ __forceinline__ uint32_t smem_u32(const void* p) {
    uint32_t a;
    asm("{ .reg .u64 t; cvta.to.shared.u64 t, %1; cvt.u32.u64 %0, t; }"
        : "=r"(a) : "l"(p));
    return a;
}
__device__ __forceinline__ void cp16(uint32_t d, const void* s) {
    asm volatile("cp.async.cg.shared.global [%0], [%1], 16;" :: "r"(d), "l"(s));
}
#define CP_COMMIT() asm volatile("cp.async.commit_group;" ::: "memory")
#define CP_WAIT(n)  asm volatile("cp.async.wait_group %0;" :: "n"(n) : "memory")

__device__ __forceinline__ void ldm4(unsigned r[4], uint32_t addr) {
    asm volatile("ldmatrix.sync.aligned.m8n8.x4.shared.b16 {%0,%1,%2,%3}, [%4];"
                 : "=r"(r[0]), "=r"(r[1]), "=r"(r[2]), "=r"(r[3]) : "r"(addr));
}

// ---------------- LayerNorm(emb[x]) ----------------
__global__ void ln_embed_kernel(const int* __restrict__ x,
                                const float* __restrict__ emb,
                                float* __restrict__ out) {
    int r = blockIdx.x;
    int tid = threadIdx.x;               // 256 threads
    int row = x[r];
    const float4* src = (const float4*)(emb + (size_t)row * EE);
    float4 v = src[tid];
    float s = v.x + v.y + v.z + v.w;
    float q = v.x * v.x + v.y * v.y + v.z * v.z + v.w * v.w;
    #pragma unroll
    for (int off = 16; off > 0; off >>= 1) {
        s += __shfl_xor_sync(0xffffffffu, s, off);
        q += __shfl_xor_sync(0xffffffffu, q, off);
    }
    __shared__ float sh_s[8], sh_q[8];
    int warp = tid >> 5, lane = tid & 31;
    if (lane == 0) { sh_s[warp] = s; sh_q[warp] = q; }
    __syncthreads();
    __shared__ float s_mu, s_inv;
    if (tid == 0) {
        float S = 0.f, Q = 0.f;
        #pragma unroll
        for (int i = 0; i < 8; i++) { S += sh_s[i]; Q += sh_q[i]; }
        float mu = S * (1.0f / EE);
        float var = Q * (1.0f / EE) - mu * mu;
        s_mu = mu;
        s_inv = rsqrtf(var + 1e-5f);
    }
    __syncthreads();
    float mu = s_mu, inv = s_inv;
    float4 o;
    o.x = (v.x - mu) * inv; o.y = (v.y - mu) * inv;
    o.z = (v.z - mu) * inv; o.w = (v.w - mu) * inv;
    ((float4*)(out + (size_t)r * EE))[tid] = o;
}

// ---------------- fp32 -> fp16 conversion ----------------
__global__ void f2h_kernel(const float* __restrict__ src,
                           __half* __restrict__ dst, int n4) {
    int i = blockIdx.x * blockDim.x + threadIdx.x;
    if (i < n4) {
        float4 v = ((const float4*)src)[i];
        __half2 h0 = __floats2half2_rn(v.x, v.y);
        __half2 h1 = __floats2half2_rn(v.z, v.w);
        uint2 o;
        o.x = *(unsigned*)&h0;
        o.y = *(unsigned*)&h1;
        ((uint2*)dst)[i] = o;
    }
}

// ---------------- fp32 SGEMM (scalar FFMA; recurrence-feeding projections) ----------------
template <int MODE>  // 1: +bias
__global__ void sgemm_tn_kernel(const float* __restrict__ A,
                                const float* __restrict__ B,
                                const float* __restrict__ bias,
                                float* __restrict__ C,
                                int M, int N, int K) {
    __shared__ float As[16][132];
    __shared__ float Bs[16][132];

    const int tid = threadIdx.x;
    const int m0 = blockIdx.x * 128;
    const int n0 = blockIdx.y * 128;
    const int tx = tid & 15;
    const int ty = tid >> 4;
    const int lr = tid >> 2;
    const int lk = (tid & 3) * 4;

    float c[8][8];
    #pragma unroll
    for (int i = 0; i < 8; i++)
        #pragma unroll
        for (int j = 0; j < 8; j++) c[i][j] = 0.f;

    for (int kt = 0; kt < K; kt += 16) {
        __syncthreads();
        float4 a0 = *(const float4*)&A[(size_t)(m0 + lr) * K + kt + lk];
        float4 a1 = *(const float4*)&A[(size_t)(m0 + lr + 64) * K + kt + lk];
        float4 b0 = *(const float4*)&B[(size_t)(n0 + lr) * K + kt + lk];
        float4 b1 = *(const float4*)&B[(size_t)(n0 + lr + 64) * K + kt + lk];
        As[lk + 0][lr] = a0.x; As[lk + 1][lr] = a0.y; As[lk + 2][lr] = a0.z; As[lk + 3][lr] = a0.w;
        As[lk + 0][lr + 64] = a1.x; As[lk + 1][lr + 64] = a1.y; As[lk + 2][lr + 64] = a1.z; As[lk + 3][lr + 64] = a1.w;
        Bs[lk + 0][lr] = b0.x; Bs[lk + 1][lr] = b0.y; Bs[lk + 2][lr] = b0.z; Bs[lk + 3][lr] = b0.w;
        Bs[lk + 0][lr + 64] = b1.x; Bs[lk + 1][lr + 64] = b1.y; Bs[lk + 2][lr + 64] = b1.z; Bs[lk + 3][lr + 64] = b1.w;
        __syncthreads();
        #pragma unroll
        for (int k = 0; k < 16; k++) {
            float4 aA = *(const float4*)&As[k][ty * 8];
            float4 aB = *(const float4*)&As[k][ty * 8 + 4];
            float4 bA = *(const float4*)&Bs[k][tx * 8];
            float4 bB = *(const float4*)&Bs[k][tx * 8 + 4];
            float a[8] = {aA.x, aA.y, aA.z, aA.w, aB.x, aB.y, aB.z, aB.w};
            float b[8] = {bA.x, bA.y, bA.z, bA.w, bB.x, bB.y, bB.z, bB.w};
            #pragma unroll
            for (int i = 0; i < 8; i++)
                #pragma unroll
                for (int j = 0; j < 8; j++)
                    c[i][j] = fmaf(a[i], b[j], c[i][j]);
        }
    }

    float bb0[8];
    if (MODE != 0) {
        float4 t0 = *(const float4*)&bias[n0 + tx * 8];
        float4 t1 = *(const float4*)&bias[n0 + tx * 8 + 4];
        bb0[0] = t0.x; bb0[1] = t0.y; bb0[2] = t0.z; bb0[3] = t0.w;
        bb0[4] = t1.x; bb0[5] = t1.y; bb0[6] = t1.z; bb0[7] = t1.w;
    }

    #pragma unroll
    for (int i = 0; i < 8; i++) {
        int row = m0 + ty * 8 + i;
        float o[8];
        #pragma unroll
        for (int j = 0; j < 8; j++) {
            float v = c[i][j];
            if (MODE != 0) v += bb0[j];
            o[j] = v;
        }
        *(float4*)&C[(size_t)row * N + n0 + tx * 8] = make_float4(o[0], o[1], o[2], o[3]);
        *(float4*)&C[(size_t)row * N + n0 + tx * 8 + 4] = make_float4(o[4], o[5], o[6], o[7]);
    }
}

// ---------------- fp16 HMMA GEMM: C[M,N] = A[M,K] * B[N,K]^T ----------------
// BM=128, BN=128, BK=32, 256 threads (2Mx4N warps, 64x32 warp tiles).
// 4-stage cp.async pipeline, 2 CTAs/SM. smem rows = 64B, swizzle c ^= (row>>1)&3.
// MODE 0: float C, plain.  MODE 2: half C, relu(x+bias).
#define H_ABYTES (128 * 64)          // 8192
#define H_BBYTES (128 * 64)          // 8192
#define H_STAGE  (H_ABYTES + H_BBYTES)
#define H_STAGES 4
#define H_SMEM   (H_STAGES * H_STAGE)   // 65536

template <int MODE>
__global__ __launch_bounds__(256, 2) void hgemm_tn_kernel(
        const __half* __restrict__ A,
        const __half* __restrict__ Bm,
        const float* __restrict__ bias,
        void* __restrict__ Cv,
        int N) {
    extern __shared__ char smem[];
    const uint32_t sb = smem_u32(smem);

    const int tid  = threadIdx.x;
    const int lane = tid & 31;
    const int warp = tid >> 5;
    const int g    = lane >> 2;
    const int tg   = lane & 3;
    const int wm   = warp & 1;     // M half (64 rows)
    const int wn   = warp >> 1;    // N quadrant (32 cols)
    const int m0 = blockIdx.x * 128;
    const int n0 = blockIdx.y * 128;

    const int li = lane & 7;
    const int lq = lane >> 3;

    float acc[4][4][4];
    #pragma unroll
    for (int i = 0; i < 4; i++)
        #pragma unroll
        for (int j = 0; j < 4; j++)
            #pragma unroll
            for (int q = 0; q < 4; q++) acc[i][j][q] = 0.f;

    auto issue = [&](int st, int kt) {
        uint32_t ab = sb + st * H_STAGE;
        uint32_t bb = ab + H_ABYTES;
        #pragma unroll
        for (int i = 0; i < 2; i++) {
            int idx = tid + i * 256;
            int row = idx >> 2, c = idx & 3;
            int sw = c ^ ((row >> 1) & 3);
            cp16(ab + row * 64 + sw * 16, &A[(size_t)(m0 + row) * GK + kt + c * 8]);
        }
        #pragma unroll
        for (int i = 0; i < 2; i++) {
            int idx = tid + i * 256;
            int row = idx >> 2, c = idx & 3;
            int sw = c ^ ((row >> 1) & 3);
            cp16(bb + row * 64 + sw * 16, &Bm[(size_t)(n0 + row) * GK + kt + c * 8]);
        }
        CP_COMMIT();
    };

    #pragma unroll
    for (int s = 0; s < H_STAGES - 1; s++) issue(s, s * 32);

    for (int ci = 0; ci < NKCH; ci++) {
        CP_WAIT(H_STAGES - 2);
        __syncthreads();
        if (ci + H_STAGES - 1 < NKCH)
            issue((ci + H_STAGES - 1) % H_STAGES, (ci + H_STAGES - 1) * 32);

        uint32_t ab = sb + (ci % H_STAGES) * H_STAGE;
        uint32_t bb = ab + H_ABYTES;

        #pragma unroll
        for (int kk = 0; kk < 2; kk++) {
            unsigned af[4][4];
            #pragma unroll
            for (int ma = 0; ma < 4; ma++) {
                int row = wm * 64 + ma * 16 + (lq & 1) * 8 + li;
                int ch  = kk * 2 + (lq >> 1);
                uint32_t ad = ab + row * 64 + ((ch ^ ((row >> 1) & 3)) * 16);
                ldm4(af[ma], ad);
            }
            unsigned bf[2][4];
            #pragma unroll
            for (int ng = 0; ng < 2; ng++) {
                int row = wn * 32 + ng * 16 + (lq >> 1) * 8 + li;
                int ch  = kk * 2 + (lq & 1);
                uint32_t bd = bb + row * 64 + ((ch ^ ((row >> 1) & 3)) * 16);
                ldm4(bf[ng], bd);
            }
            #pragma unroll
            for (int ma = 0; ma < 4; ma++)
                #pragma unroll
                for (int na = 0; na < 4; na++) {
                    const unsigned b0 = bf[na >> 1][(na & 1) * 2 + 0];
                    const unsigned b1 = bf[na >> 1][(na & 1) * 2 + 1];
                    asm volatile(
                        "mma.sync.aligned.m16n8k16.row.col.f32.f16.f16.f32 "
                        "{%0,%1,%2,%3}, {%4,%5,%6,%7}, {%8,%9}, {%0,%1,%2,%3};\n"
                        : "+f"(acc[ma][na][0]), "+f"(acc[ma][na][1]),
                          "+f"(acc[ma][na][2]), "+f"(acc[ma][na][3])
                        : "r"(af[ma][0]), "r"(af[ma][1]), "r"(af[ma][2]), "r"(af[ma][3]),
                          "r"(b0), "r"(b1));
                }
        }
    }

    #pragma unroll
    for (int ma = 0; ma < 4; ma++) {
        int r0 = m0 + wm * 64 + ma * 16 + g;
        #pragma unroll
        for (int na = 0; na < 4; na++) {
            int c0 = n0 + wn * 32 + na * 8 + tg * 2;
            float v0 = acc[ma][na][0], v1 = acc[ma][na][1];
            float v2 = acc[ma][na][2], v3 = acc[ma][na][3];
            if (MODE == 2) {
                __half* C = (__half*)Cv;
                float bz0 = __ldg(&bias[c0]), bz1 = __ldg(&bias[c0 + 1]);
                __half2 h0 = __floats2half2_rn(fmaxf(v0 + bz0, 0.f), fmaxf(v1 + bz1, 0.f));
                __half2 h2 = __floats2half2_rn(fmaxf(v2 + bz0, 0.f), fmaxf(v3 + bz1, 0.f));
                *(__half2*)&C[(size_t)r0 * N + c0]       = h0;
                *(__half2*)&C[(size_t)(r0 + 8) * N + c0] = h2;
            } else {
                float* C = (float*)Cv;
                *(float2*)&C[(size_t)r0 * N + c0]       = make_float2(v0, v1);
                *(float2*)&C[(size_t)(r0 + 8) * N + c0] = make_float2(v2, v3);
            }
        }
    }
}

// ---------------- flag reset ----------------
__global__ void reset_flags_kernel() {
    g_ready[threadIdx.x] = 0u;
    if (threadIdx.x == 0) g_master = 0u;
}

// ---------------- Persistent RNN recurrence ----------------
// Leader-based grid barrier (proven in round 7): each CTA posts its flag;
// CTA0 aggregates and publishes a single master epoch; others poll one word.
__global__ __launch_bounds__(256, 1) void rnn_recurrence_kernel(
        const float* __restrict__ xp,
        const float* __restrict__ Whh,
        const float* __restrict__ bhh,
        float* __restrict__ hout) {
    __shared__ float h_s[BB][HH];       // 32 KB
    __shared__ float part[2][8][BB];

    const int tid = threadIdx.x;
    const int warp = tid >> 5, lane = tid & 31;
    const int rp = warp >> 1;
    const int fh = warp & 1;
    const int r0 = blockIdx.x * 8 + rp * 2;

    float4 W0[4], W1[4];
    #pragma unroll
    for (int it = 0; it < 4; it++) {
        int f = fh * 512 + it * 128 + lane * 4;
        W0[it] = *(const float4*)&Whh[(size_t)r0 * HH + f];
        W1[it] = *(const float4*)&Whh[(size_t)(r0 + 1) * HH + f];
    }

    // epilogue constants (tid < 64 writes h rows)
    const int lrow = tid >> 3, bidx = tid & 7;
    const int rg = blockIdx.x * 8 + lrow;
    const float bconst = (tid < 64) ? bhh[rg] : 0.f;

    for (int t = 0; t < TT; t++) {
        // prefetch xp for this step (independent of h chain)
        float xpv = 0.f;
        if (tid < 64)
            xpv = __ldcg(&xp[((size_t)(bidx * TT + t) << 10) + rg]);

        // stage h_{t-1} into shared (zeros for t=0)
        #pragma unroll
        for (int i = 0; i < 8; i++) {
            int idx = tid + i * 256;
            float4 v;
            if (t == 0) {
                v = make_float4(0.f, 0.f, 0.f, 0.f);
            } else {
                int b = idx >> 8, f4 = idx & 255;
                v = __ldcg((const float4*)&hout[((size_t)(b * TT + t - 1) << 10) + (f4 << 2)]);
            }
            ((float4*)h_s)[idx] = v;
        }
        __syncthreads();

        float acc0[BB], acc1[BB];
        #pragma unroll
        for (int b = 0; b < BB; b++) { acc0[b] = 0.f; acc1[b] = 0.f; }
        #pragma unroll
        for (int it = 0; it < 4; it++) {
            int f = fh * 512 + it * 128 + lane * 4;
            float4 w0 = W0[it], w1 = W1[it];
            #pragma unroll
            for (int b = 0; b < BB; b++) {
                float4 h4 = *(const float4*)&h_s[b][f];
                acc0[b] += w0.x * h4.x + w0.y * h4.y + w0.z * h4.z + w0.w * h4.w;
                acc1[b] += w1.x * h4.x + w1.y * h4.y + w1.z * h4.z + w1.w * h4.w;
            }
        }
        #pragma unroll
        for (int off = 16; off > 0; off >>= 1) {
            #pragma unroll
            for (int b = 0; b < BB; b++) {
                acc0[b] += __shfl_xor_sync(0xffffffffu, acc0[b], off);
                acc1[b] += __shfl_xor_sync(0xffffffffu, acc1[b], off);
            }
        }
        if (lane == 0) {
            #pragma unroll
            for (int b = 0; b < BB; b++) {
                part[fh][rp * 2][b] = acc0[b];
                part[fh][rp * 2 + 1][b] = acc1[b];
            }
        }
        __syncthreads();

        if (tid < 64) {
            float v = part[0][lrow][bidx] + part[1][lrow][bidx] + xpv + bconst;
            hout[((size_t)(bidx * TT + t) << 10) + rg] = tanhf(v);
            __threadfence();
        }
        __syncthreads();

        // ---- leader grid barrier (round-7 proven) ----
        if (tid == 0) {
            __threadfence();
            g_ready[blockIdx.x] = (unsigned)(t + 1);   // publish arrival
        }
        if (blockIdx.x == 0) {
            if (tid < RNN_NBLK) {
                while (g_ready[tid] < (unsigned)(t + 1)) { }
            }
            __threadfence();
            __syncthreads();
            if (tid == 0) g_master = (unsigned)(t + 1);
            __syncthreads();
        } else {
            if (tid == 0) {
                while (g_master < (unsigned)(t + 1)) { }
                __threadfence();
            }
            __syncthreads();
        }
    }
}

// ---------------- launch ----------------
extern "C" void kernel_launch(void* const* d_in, const int* in_sizes, int n_in,
                              void* d_out, int out_size) {
    const int*   x      = (const int*)d_in[0];
    const float* emb    = (const float*)d_in[1];
    const float* W_ih0  = (const float*)d_in[2];
    const float* W_hh0  = (const float*)d_in[3];
    const float* b_ih0  = (const float*)d_in[4];
    const float* b_hh0  = (const float*)d_in[5];
    const float* W_ih1  = (const float*)d_in[6];
    const float* W_hh1  = (const float*)d_in[7];
    const float* b_ih1  = (const float*)d_in[8];
    const float* b_hh1  = (const float*)d_in[9];
    const float* W_lin  = (const float*)d_in[10];
    const float* b_lin  = (const float*)d_in[11];
    float* out = (float*)d_out;

    float *xnorm, *xp, *h0, *h1;
    __half *embh, *wlh, *h1h, *acth;
    cudaGetSymbolAddress((void**)&xnorm, g_xnorm);
    cudaGetSymbolAddress((void**)&xp,    g_xp);
    cudaGetSymbolAddress((void**)&h0,    g_h0);
    cudaGetSymbolAddress((void**)&h1,    g_h1);
    cudaGetSymbolAddress((void**)&embh,  g_embh);
    cudaGetSymbolAddress((void**)&wlh,   g_wlh);
    cudaGetSymbolAddress((void**)&h1h,   g_h1h);
    cudaGetSymbolAddress((void**)&acth,  g_acth);

    cudaFuncSetAttribute(hgemm_tn_kernel<0>, cudaFuncAttributeMaxDynamicSharedMemorySize, H_SMEM);
    cudaFuncSetAttribute(hgemm_tn_kernel<2>, cudaFuncAttributeMaxDynamicSharedMemorySize, H_SMEM);

    // 0. fp16 conversions (independent of the sequential chain)
    f2h_kernel<<<(VV * EE / 4 + 255) / 256, 256>>>(emb, embh, VV * EE / 4);
    f2h_kernel<<<(EE * HH / 4 + 255) / 256, 256>>>(W_lin, wlh, EE * HH / 4);

    // 1. xnorm = LN(emb[x])
    ln_embed_kernel<<<MTOK, 256>>>(x, emb, xnorm);

    // 2. xp = xnorm @ W_ih0^T + b_ih0   (fp32)
    {
        dim3 grid(MTOK / 128, HH / 128);
        sgemm_tn_kernel<1><<<grid, 256>>>(xnorm, W_ih0, b_ih0, xp, MTOK, HH, EE);
    }

    // 3. layer 0 recurrence
    reset_flags_kernel<<<1, RNN_NBLK>>>();
    rnn_recurrence_kernel<<<RNN_NBLK, 256>>>(xp, W_hh0, b_hh0, h0);

    // 4. xp = h0 @ W_ih1^T + b_ih1   (fp32)
    {
        dim3 grid(MTOK / 128, HH / 128);
        sgemm_tn_kernel<1><<<grid, 256>>>(h0, W_ih1, b_ih1, xp, MTOK, HH, HH);
    }

    // 5. layer 1 recurrence
    reset_flags_kernel<<<1, RNN_NBLK>>>();
    rnn_recurrence_kernel<<<RNN_NBLK, 256>>>(xp, W_hh1, b_hh1, h1);

    // 5b. h1 -> fp16
    f2h_kernel<<<(MTOK * HH / 4 + 255) / 256, 256>>>(h1, h1h, MTOK * HH / 4);

    // 6. acth = relu(h1h @ wlh^T + b_lin)   (fp16 HMMA, fp16 out)
    {
        dim3 grid(MTOK / 128, EE / 128);
        hgemm_tn_kernel<2><<<grid, 256, H_SMEM>>>(h1h, wlh, b_lin, acth, EE);
    }

    // 7. out = acth @ embh^T   [4096, 32000]  (fp16 HMMA, fp32 out)
    {
        dim3 grid(MTOK / 128, VV / 128);
        hgemm_tn_kernel<0><<<grid, 256, H_SMEM>>>(acth, embh, nullptr, out, VV);
    }
}